// round 17
// baseline (speedup 1.0000x reference)
#include <cuda_runtime.h>

// Geometry: (1, D=24, H=24, W=16, C=2); N = 9216 voxels. i = z*384 + y*16 + x.
#define NV   9216
#define NB   144     // <= 148 SMs: all co-resident (safe persistent barriers)
#define NT   384
#define GPERL 720    // global-counter increments per launch: 5 barriers * 144
#define LPERL 24     // local-counter increments per launch:  4 barriers * 6

// Taylor rank-5 factorization of the bilateral intensity kernel:
//   exp(-(Ii-Ij)^2/18) = e^{-Ii^2/18} e^{-Ij^2/18} * sum_k c_k Ii^k Ij^k  (err ~1.4e-7)
// 12 fields: bilateral f = 2k+c (k=0..4), spatial f = 10+c. Stored as 6
// float2 PAIR fields P = f>>1 (classes in .x/.y). Block b: f0 = b/24 owns
// fields f0 (pair f0>>1) and f0+6 (pair 3+(f0>>1)), element c = f0&1;
// slab/plane z = b%24. Phase 2 re-role: chunk c2 = f0, output slab z.

__device__ float2 g_xy2[2][6][NV];  // ping-pong xy-blurred pair fields
__device__ float  g_xyn[5][NV];     // xy-blurred norm basis (round 1 only)
__device__ float2 g_q[NV];          // q field (both classes)
__device__ int    g_gcnt;           // global barrier counter (monotonic RMW chain)
__device__ int    g_lcnt[24][32];   // per-z-set local counters, 128B apart

__device__ __forceinline__ int ld_acq(const int* p) {
    int v; asm volatile("ld.global.acquire.gpu.b32 %0, [%1];" : "=r"(v) : "l"(p) : "memory");
    return v;
}
// Release-RMW arrive: one increment on a single line. An acquire load that
// observes the final value of the RMW chain synchronizes with EVERY
// release-RMW in it (release sequences are preserved by RMWs), so one poll
// load proves all arrivals' prior stores visible.
__device__ __forceinline__ void red_rel(int* p, int v) {
    asm volatile("red.release.gpu.global.add.s32 [%0], %1;" :: "l"(p), "r"(v) : "memory");
}

// f32x2 packed helpers (ptxas won't auto-fuse; PTX-only path).
__device__ __forceinline__ unsigned long long lds2(const float2* p) {
    unsigned long long v;
    asm volatile("ld.shared.b64 %0, [%1];" : "=l"(v)
                 : "r"((unsigned)__cvta_generic_to_shared(p)));
    return v;
}
__device__ __forceinline__ void ffma2(unsigned long long& d,
                                      unsigned long long a, unsigned long long b) {
    asm volatile("fma.rn.f32x2 %0, %1, %2, %0;" : "+l"(d) : "l"(a), "l"(b));
}
__device__ __forceinline__ float2 u2f2(unsigned long long v) {
    float2 r;
    r.x = __uint_as_float((unsigned)v);
    r.y = __uint_as_float((unsigned)(v >> 32));
    return r;
}

// ---------------------------------------------------------------------------
// Per round r: phase1 (load q, shfl x-pass + smem y-pass of 2 fields, slab z)
// -> global arrive [r==1: overlap phase2-setup] wait -> phase2 (z-contract
// pair j over 64-voxel chunk, finalize q or write out) -> LOCAL(6).
// 5 global + 4 local syncs, all on single-counter release-RMW chains.
// ---------------------------------------------------------------------------
__global__ void __launch_bounds__(NT, 1)
crf_kernel(const float* __restrict__ u, const float* __restrict__ rgb,
           const float* __restrict__ ws, const float* __restrict__ wb,
           const float* __restrict__ Mc, float* __restrict__ out)
{
    __shared__ float  kb24[576], ks24[576];   // raw axis kernels (theta=160 / 3)
    __shared__ float  kb16[256], ks16[256];
    __shared__ float2 kp16[256], kp24[576];   // packed (kb, unit1-kernel)
    __shared__ float2 Spair[384], Tpair[384]; // phase2 partials / y-pass stage
    __shared__ float  T2[384];                // round-1 norm path

    const int b = blockIdx.x, t = threadIdx.x;
    const int f0 = b / 24, z = b % 24;

    // Replay-safe counter bases (thread 0 only). Counters advance exactly
    // GPERL / LPERL per launch and launches are stream-serialized, so during
    // launch n the values lie in [n*PERL, (n+1)*PERL) -> floor recovers base.
    int gbase = 0, lbase = 0, tg = 0, tl = 0;
    if (t == 0) {
        gbase = (ld_acq(&g_gcnt) / GPERL) * GPERL;
        lbase = (ld_acq(&g_lcnt[z][0]) / LPERL) * LPERL;
    }

    const int c  = f0 & 1;
    const bool bil1 = (f0 < 4);        // unit1 field f0+6 bilateral?
    const int P0 = f0 >> 1, P1 = 3 + (f0 >> 1);

    for (int idx = t; idx < 576; idx += NT) {
        float d = (float)(idx / 24) - (float)(idx % 24), d2 = d * d;
        float kb = __expf(-d2 * (0.5f / 25600.f));
        float ks = __expf(-d2 * (0.5f / 9.f));
        kb24[idx] = kb; ks24[idx] = ks;
        kp24[idx] = make_float2(kb, bil1 ? kb : ks);
    }
    for (int idx = t; idx < 256; idx += NT) {
        float d = (float)(idx / 16) - (float)(idx % 16), d2 = d * d;
        float kb = __expf(-d2 * (0.5f / 25600.f));
        float ks = __expf(-d2 * (0.5f / 9.f));
        kb16[idx] = kb; ks16[idx] = ks;
        kp16[idx] = make_float2(kb, bil1 ? kb : ks);
    }
    __syncthreads();

    const float ws0 = ws[0], ws1 = ws[1], wb0 = wb[0], wb1 = wb[1];
    const float M00 = Mc[0], M01 = Mc[1], M10 = Mc[2], M11 = Mc[3];

    // ---- phase1 per-thread constants (voxel i1 in slab z) ----
    const int i1 = z * 384 + t;
    const int yy = t >> 4, xx = t & 15;
    const float Iv = rgb[i1];
    const float eI = __expf(-(1.f / 18.f) * Iv * Iv);
    float Ip[5]; Ip[0] = 1.f;
    #pragma unroll
    for (int k = 1; k < 5; ++k) Ip[k] = Ip[k - 1] * Iv;
    const float bf0 = eI * Ip[f0 >> 1];                    // field f0 (k = f0>>1)
    const float bf1 = bil1 ? eI * Ip[(f0 + 6) >> 1] : 1.f; // field f0+6
    const float bfn = (f0 < 5) ? eI * Ip[f0] : 0.f;        // norm basis (r1)
    const float u_c = u[2 * i1 + c];

    // ---- phase2 thread roles (cheap index math only; heavy setup deferred) --
    const int vv = t & 63, j = t >> 6;       // pair index 0..5
    const int c2 = f0;                       // chunk id
    const int cv = c2 * 64 + vv;             // slab-local column
    const int i2 = z * 384 + c2 * 64 + t;    // finalizer voxel (t<64)

    // Deferred phase2 setup (filled in round-1 barrier gap):
    float kw[24];
    float ckIp2[5], inv_ns2 = 0.f, inv_nb = 0.f, u20 = 0.f, u21 = 0.f;

    #pragma unroll
    for (int r = 1; r <= 5; ++r) {
        const int side = r & 1;
        // ------------- phase 1: q + shfl x-pass + smem y-pass -------------
        float q;
        if (r == 1) {
            q = u_c;
        } else {
            float2 qv = __ldcg(&g_q[i1]);
            q = (c == 0) ? qv.x : qv.y;
        }
        {   // x-pass via half-warp shuffles (row = 16 lanes), no smem stage
            unsigned vlo = __float_as_uint(bf0 * q);
            unsigned vhi = __float_as_uint(bf1 * q);
            float vn = bfn;                   // round-1 norm value
            unsigned long long acc = 0ull;
            float a2 = 0.f;
            const float2* kbase = kp16 + xx;
            #pragma unroll
            for (int xp = 0; xp < 16; ++xp) {
                unsigned slo = __shfl_sync(0xffffffffu, vlo, xp, 16);
                unsigned shi = __shfl_sync(0xffffffffu, vhi, xp, 16);
                unsigned long long sv = (unsigned long long)slo
                                      | ((unsigned long long)shi << 32);
                ffma2(acc, lds2(kbase + xp * 16), sv);
                if (r == 1 && f0 < 5) {
                    float sn = __shfl_sync(0xffffffffu, vn, xp, 16);
                    a2 += kb16[xp * 16 + xx] * sn;
                }
            }
            Tpair[t] = u2f2(acc);
            if (r == 1) T2[t] = a2;
        }
        __syncthreads();
        {   // y-pass + global store
            unsigned long long acc = 0ull;
            const float2* kbase = kp24 + yy;
            const float2* sbase = Tpair + xx;
            #pragma unroll
            for (int yp = 0; yp < 24; ++yp)
                ffma2(acc, lds2(kbase + yp * 24), lds2(sbase + (yp << 4)));
            float2 o = u2f2(acc);
            reinterpret_cast<float*>(&g_xy2[side][P0][i1])[c] = o.x;
            reinterpret_cast<float*>(&g_xy2[side][P1][i1])[c] = o.y;
            if (r == 1 && f0 < 5) {
                float o2 = 0.f;
                #pragma unroll
                for (int yp = 0; yp < 24; ++yp)
                    o2 += kb24[yp * 24 + yy] * T2[(yp << 4) + xx];
                g_xyn[f0][i1] = o2;
            }
        }
        // ---- global arrive ----
        __syncthreads();                       // block's field stores issued
        tg += 1;
        if (t == 0) red_rel(&g_gcnt, 1);
        if (r == 1) {
            // ---- phase2 setup, hidden in the barrier's skew/detect gap ----
            {   // register-hoisted z-contract weights (constant across rounds)
                const float* kcol = ((j < 5) ? kb24 : ks24) + z;
                #pragma unroll
                for (int zp = 0; zp < 24; ++zp) kw[zp] = kcol[zp * 24];
            }
            if (t < 64) {
                float I2 = rgb[i2];
                const float ck[5] = {1.f, 0.111111111f, 0.0061728395f,
                                     2.28623686e-4f, 6.35066338e-6f};
                float p = 1.f;
                #pragma unroll
                for (int k = 0; k < 5; ++k) { ckIp2[k] = ck[k] * p; p *= I2; }
                float2 uu = reinterpret_cast<const float2*>(u)[i2];
                u20 = uu.x; u21 = uu.y;
                int y2 = (c2 * 64 + t) >> 4, x2 = (c2 * 64 + t) & 15;
                float Sz = 0.f, Sy = 0.f, Sx = 0.f;  // exact spatial norm
                #pragma unroll
                for (int p24 = 0; p24 < 24; ++p24) {
                    Sz += ks24[p24 * 24 + z]; Sy += ks24[p24 * 24 + y2];
                }
                #pragma unroll
                for (int p16 = 0; p16 < 16; ++p16) Sx += ks16[p16 * 16 + x2];
                inv_ns2 = 1.f / (Sz * Sy * Sx);
            }
        }
        // ---- global wait: one line, one poller ----
        if (t == 0) {
            const int target = gbase + NB * tg;
            while (ld_acq(&g_gcnt) < target) {}
        }
        __syncthreads();

        // ------------- phase 2: z-contract pair j over chunk, finalize -------------
        {
            float b0 = 0.f, b1 = 0.f;
            const float2* src = &g_xy2[side][j][cv];
            #pragma unroll
            for (int zp = 0; zp < 24; ++zp) {
                float2 vq = __ldcg(src + zp * 384);
                b0 += kw[zp] * vq.x; b1 += kw[zp] * vq.y;
            }
            Spair[(j << 6) + vv] = make_float2(b0, b1);
            if (r == 1 && j < 5) {
                float bn = 0.f;
                #pragma unroll
                for (int zp = 0; zp < 24; ++zp)
                    bn += kw[zp] * __ldcg(&g_xyn[j][zp * 384 + cv]);
                T2[(j << 6) + vv] = bn;   // j<5 uses kb24 weights (bilateral)
            }
        }
        __syncthreads();
        if (t < 64) {
            float bb0 = 0.f, bb1 = 0.f;
            #pragma unroll
            for (int k = 0; k < 5; ++k) {
                float2 s = Spair[(k << 6) + t];
                bb0 += ckIp2[k] * s.x;
                bb1 += ckIp2[k] * s.y;
            }
            if (r == 1) {
                float nb = 0.f;
                #pragma unroll
                for (int k = 0; k < 5; ++k) nb += ckIp2[k] * T2[(k << 6) + t];
                inv_nb = 1.f / nb;
            }
            float2 sp = Spair[(5 << 6) + t];
            float m0 = sp.x * inv_ns2 * ws0 + bb0 * inv_nb * wb0;
            float m1 = sp.y * inv_ns2 * ws1 + bb1 * inv_nb * wb1;
            float2 qv;
            qv.x = u20 - (m0 * M00 + m1 * M01);
            qv.y = u21 - (m0 * M10 + m1 * M11);
            if (r == 5) reinterpret_cast<float2*>(out)[i2] = qv;
            else        g_q[i2] = qv;
        }
        if (r < 5) {
            // ---- local(6) barrier on per-z counter ----
            __syncthreads();               // finalize q stores issued
            tl += 1;
            if (t == 0) {
                red_rel(&g_lcnt[z][0], 1);
                const int ltarget = lbase + 6 * tl;
                while (ld_acq(&g_lcnt[z][0]) < ltarget) {}
            }
            __syncthreads();
        }
    }
}

// ---------------------------------------------------------------------------
// Inputs (metadata order): unaries[18432] f32, rgb[9216] f32,
// spatial_ker_weights[2] f32, bilateral_ker_weights[2] f32,
// compatibility_matrix[4] f32 (row-major). Output: float32 [18432].
// ---------------------------------------------------------------------------
extern "C" void kernel_launch(void* const* d_in, const int* in_sizes, int n_in,
                              void* d_out, int out_size) {
    const float* u   = (const float*)d_in[0];
    const float* rgb = (const float*)d_in[1];
    const float* ws  = (const float*)d_in[2];
    const float* wb  = (const float*)d_in[3];
    const float* Mc  = (const float*)d_in[4];
    crf_kernel<<<NB, NT>>>(u, rgb, ws, wb, Mc, (float*)d_out);
}